// round 16
// baseline (speedup 1.0000x reference)
#include <cuda_runtime.h>
#include <cuda_fp16.h>
#include <math_constants.h>
#include <cstdint>

#define BB   8
#define TT   1024
#define CC   768
#define HH   12
#define HD   64
#define MM   (BB * TT)       // 8192
#define N3   (3 * CC)        // 2304

// ---------------------------------------------------------------------------
// Static device scratch (addresses formed ONLY in device code)
// ---------------------------------------------------------------------------
__device__ __align__(16) __half g_qh[BB * HH * TT * HD];  // [bh][t][d] split hi (pre-scaled 1/8)
__device__ __align__(16) __half g_ql[BB * HH * TT * HD];  // split lo
__device__ __align__(16) __half g_k [BB * HH * TT * HD];  // [bh][t][d] single fp16
__device__ __align__(16) __half g_vt[BB * HH * HD * TT];  // [bh][d][t] single fp16 (transposed)

__device__ __align__(16) __half g_xh[MM * CC];            // X split hi
__device__ __align__(16) __half g_xl[MM * CC];            // X split lo
__device__ __align__(16) __half g_wa[N3 * CC];            // W_attn^T [N3][CC] single fp16
__device__ __align__(16) __half g_wp[CC * CC];            // W_proj^T single fp16
__device__ __align__(16) __half g_yh[MM * CC];            // y split hi
__device__ __align__(16) __half g_yl[MM * CC];            // y split lo

// ---------------------------------------------------------------------------
// PTX helpers
// ---------------------------------------------------------------------------
__device__ __forceinline__ uint32_t smem_u32(const void* p) {
    uint32_t a;
    asm("{ .reg .u64 t; cvta.to.shared.u64 t, %1; cvt.u32.u64 %0, t; }" : "=r"(a) : "l"(p));
    return a;
}
__device__ __forceinline__ void ldm_x4(uint32_t* r, uint32_t addr) {
    asm volatile("ldmatrix.sync.aligned.m8n8.x4.shared.b16 {%0,%1,%2,%3}, [%4];"
                 : "=r"(r[0]), "=r"(r[1]), "=r"(r[2]), "=r"(r[3]) : "r"(addr));
}
__device__ __forceinline__ void mma_f16(float* d, const uint32_t* a, const uint32_t* b,
                                        const float* c) {
    asm volatile("mma.sync.aligned.m16n8k16.row.col.f32.f16.f16.f32 "
                 "{%0,%1,%2,%3}, {%4,%5,%6,%7}, {%8,%9}, {%10,%11,%12,%13};"
                 : "=f"(d[0]), "=f"(d[1]), "=f"(d[2]), "=f"(d[3])
                 : "r"(a[0]), "r"(a[1]), "r"(a[2]), "r"(a[3]), "r"(b[0]), "r"(b[1]),
                   "f"(c[0]), "f"(c[1]), "f"(c[2]), "f"(c[3]));
}
__device__ __forceinline__ void cp16(uint32_t dst, const void* src) {
    asm volatile("cp.async.cg.shared.global [%0], [%1], 16;" :: "r"(dst), "l"(src));
}
__device__ __forceinline__ void cp_commit() {
    asm volatile("cp.async.commit_group;" ::: "memory");
}
template <int N>
__device__ __forceinline__ void cp_wait() {
    asm volatile("cp.async.wait_group %0;" :: "n"(N) : "memory");
}

// Fast exp: magic-number round + degree-5 poly for 2^f. Abs err ~2.4e-6.
__device__ __forceinline__ float fast_exp(float x) {
    x = fmaxf(x, -87.0f);
    float t = x * 1.4426950408889634f;
    float k = t + 12582912.0f;                 // 1.5 * 2^23
    int   e = __float_as_int(k) - 0x4B400000;
    float f = t - (k - 12582912.0f);
    float p = 1.3333558146e-3f;
    p = fmaf(p, f, 9.6181291076e-3f);
    p = fmaf(p, f, 5.5504108665e-2f);
    p = fmaf(p, f, 2.4022650696e-1f);
    p = fmaf(p, f, 6.9314718056e-1f);
    p = fmaf(p, f, 1.0f);
    return __int_as_float(__float_as_int(p) + (e << 23));
}
__device__ __forceinline__ uint32_t packh(__half a, __half b) {
    __half2 h(a, b);
    return *(uint32_t*)&h;
}

// ---------------------------------------------------------------------------
// fp16 GEMM core: 2-pass (A split hi/lo, B single), k-chunk = 64,
// 2-stage cp.async, ldmatrix fragments. Tiles: 128 rows x 64 fp16, pitch 144 B.
// ---------------------------------------------------------------------------
#define GROWB     144
#define GTILE_B   (128 * GROWB)         // 18432
#define GSTAGE_B  (3 * GTILE_B)         // Ah, Al, B = 55296
#define GEMM_SMEM (2 * GSTAGE_B)        // 110592
#define NITER     (CC / 64)             // 12

__device__ __forceinline__ void load_stage(const __half* Ah, const __half* Al,
                                           const __half* B,
                                           int m0, int n0, int k0,
                                           uint32_t sbase, int tid) {
    const __half* srcs[3] = {Ah + (size_t)m0 * CC, Al + (size_t)m0 * CC,
                             B + (size_t)n0 * CC};
#pragma unroll
    for (int i = 0; i < 12; i++) {
        int e = tid + i * 256;            // 0..3071
        int t = e >> 10;                  // tile 0..2
        int idx = e & 1023;
        int row = idx >> 3, c = idx & 7;  // 8 x 16B per row
        cp16(sbase + t * GTILE_B + row * GROWB + c * 16,
             srcs[t] + (size_t)row * CC + k0 + c * 8);
    }
}

__device__ __forceinline__ void gemm_compute(uint32_t stage, int lane, int wm, int wn,
                                             float acc[4][4][4]) {
    const uint32_t sAh = stage;
    const uint32_t sAl = stage + GTILE_B;
    const uint32_t sB  = stage + 2 * GTILE_B;
    const int arow = lane & 15;
    const int achunk = lane >> 4;                     // 0/1 -> +16B (k8-15)
    const int brow = (lane & 7) + ((lane >> 4) << 3); // phases: n0-7,n0-7,n8-15,n8-15
    const int bchunk = (lane >> 3) & 1;

#pragma unroll
    for (int kk = 0; kk < 4; kk++) {
        const uint32_t aoff = kk * 32 + achunk * 16;
        const uint32_t boff = kk * 32 + bchunk * 16;
        uint32_t ah[4][4], al[4][4], bb[2][4];
#pragma unroll
        for (int bj = 0; bj < 2; bj++)
            ldm_x4(bb[bj], sB + (wn + bj * 16 + brow) * GROWB + boff);
#pragma unroll
        for (int mi = 0; mi < 4; mi++) {
            ldm_x4(ah[mi], sAh + (wm + mi * 16 + arow) * GROWB + aoff);
            ldm_x4(al[mi], sAl + (wm + mi * 16 + arow) * GROWB + aoff);
        }
#pragma unroll
        for (int mi = 0; mi < 4; mi++)
#pragma unroll
            for (int nj = 0; nj < 4; nj++) {
                mma_f16(acc[mi][nj], ah[mi], &bb[nj >> 1][(nj & 1) * 2], acc[mi][nj]);
                mma_f16(acc[mi][nj], al[mi], &bb[nj >> 1][(nj & 1) * 2], acc[mi][nj]);
            }
    }
}

__device__ __forceinline__ void gemm_mainloop(const __half* Ah, const __half* Al,
                                              const __half* B,
                                              int m0, int n0, char* sm,
                                              int tid, int lane, int wm, int wn,
                                              float acc[4][4][4]) {
    const uint32_t sbase = smem_u32(sm);
    load_stage(Ah, Al, B, m0, n0, 0, sbase, tid);
    cp_commit();
    for (int c = 0; c < NITER; c++) {
        if (c + 1 < NITER) {
            load_stage(Ah, Al, B, m0, n0, (c + 1) * 64,
                       sbase + ((c + 1) & 1) * GSTAGE_B, tid);
            cp_commit();
            cp_wait<1>();
        } else {
            cp_wait<0>();
        }
        __syncthreads();
        gemm_compute(sbase + (c & 1) * GSTAGE_B, lane, wm, wn, acc);
        __syncthreads();
    }
}

// ---------------------------------------------------------------------------
// QKV GEMM -> q split fp16 (scaled), k single fp16, v single fp16 transposed
// ---------------------------------------------------------------------------
__global__ __launch_bounds__(256, 2) void qkv_mm(const float* __restrict__ bias)
{
    extern __shared__ char sm[];
    const int tid = threadIdx.x, lane = tid & 31, wid = tid >> 5;
    const int wm = (wid & 1) * 64, wn = (wid >> 1) * 32;
    const int m0 = blockIdx.y * 128, n0 = blockIdx.x * 128;

    float acc[4][4][4];
#pragma unroll
    for (int a = 0; a < 4; a++)
#pragma unroll
        for (int b = 0; b < 4; b++)
#pragma unroll
            for (int c = 0; c < 4; c++) acc[a][b][c] = 0.f;

    gemm_mainloop(g_xh, g_xl, g_wa, m0, n0, sm, tid, lane, wm, wn, acc);

    const int g = lane >> 2, t4 = lane & 3;
    const int which = blockIdx.x / 6;
#pragma unroll
    for (int mi = 0; mi < 4; mi++) {
#pragma unroll
        for (int half = 0; half < 2; half++) {
            const int m = m0 + wm + mi * 16 + g + half * 8;
            const int b_ = m >> 10, t = m & 1023;
#pragma unroll
            for (int nj = 0; nj < 4; nj++) {
                const int n = n0 + wn + nj * 8 + t4 * 2;
                float vx = acc[mi][nj][half * 2 + 0] + __ldg(bias + n);
                float vy = acc[mi][nj][half * 2 + 1] + __ldg(bias + n + 1);
                const int ccol = n - which * CC;
                const int h = ccol >> 6, d = ccol & 63;
                const int bh = b_ * HH + h;
                if (which == 0) {
                    vx *= 0.125f; vy *= 0.125f;
                    __half hx = __float2half_rn(vx), hy = __float2half_rn(vy);
                    __half lx = __float2half_rn(vx - __half2float(hx));
                    __half ly = __float2half_rn(vy - __half2float(hy));
                    size_t o0 = ((size_t)bh * TT + t) * HD + d;
                    *(__half2*)(g_qh + o0) = __half2(hx, hy);
                    *(__half2*)(g_ql + o0) = __half2(lx, ly);
                } else if (which == 1) {
                    size_t o0 = ((size_t)bh * TT + t) * HD + d;
                    *(__half2*)(g_k + o0) = __floats2half2_rn(vx, vy);
                } else {
                    size_t o0 = ((size_t)bh * HD + d) * TT + t;
                    g_vt[o0]      = __float2half_rn(vx);
                    g_vt[o0 + TT] = __float2half_rn(vy);
                }
            }
        }
    }
}

// ---------------------------------------------------------------------------
// Proj GEMM -> out fp32 [M][CC] with bias
// ---------------------------------------------------------------------------
__global__ __launch_bounds__(256, 2) void proj_mm(const float* __restrict__ bias,
                                                  float* __restrict__ out)
{
    extern __shared__ char sm[];
    const int tid = threadIdx.x, lane = tid & 31, wid = tid >> 5;
    const int wm = (wid & 1) * 64, wn = (wid >> 1) * 32;
    const int m0 = blockIdx.y * 128, n0 = blockIdx.x * 128;

    float acc[4][4][4];
#pragma unroll
    for (int a = 0; a < 4; a++)
#pragma unroll
        for (int b = 0; b < 4; b++)
#pragma unroll
            for (int c = 0; c < 4; c++) acc[a][b][c] = 0.f;

    gemm_mainloop(g_yh, g_yl, g_wp, m0, n0, sm, tid, lane, wm, wn, acc);

    const int g = lane >> 2, t4 = lane & 3;
#pragma unroll
    for (int mi = 0; mi < 4; mi++) {
#pragma unroll
        for (int half = 0; half < 2; half++) {
            const int m = m0 + wm + mi * 16 + g + half * 8;
#pragma unroll
            for (int nj = 0; nj < 4; nj++) {
                const int n = n0 + wn + nj * 8 + t4 * 2;
                float2 v;
                v.x = acc[mi][nj][half * 2 + 0] + __ldg(bias + n);
                v.y = acc[mi][nj][half * 2 + 1] + __ldg(bias + n + 1);
                *(float2*)(out + (size_t)m * CC + n) = v;
            }
        }
    }
}

// ---------------------------------------------------------------------------
// Conversion kernels (globals referenced from device code only)
// ---------------------------------------------------------------------------
__global__ void split_x_kernel(const float* __restrict__ src)
{
    int i = blockIdx.x * blockDim.x + threadIdx.x;
    if (i >= MM * CC / 4) return;
    float4 v = ((const float4*)src)[i];
    __half h0 = __float2half_rn(v.x);
    __half h1 = __float2half_rn(v.y);
    __half h2 = __float2half_rn(v.z);
    __half h3 = __float2half_rn(v.w);
    __half2* hp = (__half2*)g_xh;
    __half2* lp = (__half2*)g_xl;
    hp[i * 2 + 0] = __half2(h0, h1);
    hp[i * 2 + 1] = __half2(h2, h3);
    lp[i * 2 + 0] = __half2(__float2half_rn(v.x - __half2float(h0)),
                            __float2half_rn(v.y - __half2float(h1)));
    lp[i * 2 + 1] = __half2(__float2half_rn(v.z - __half2float(h2)),
                            __float2half_rn(v.w - __half2float(h3)));
}

// W[K=CC][N] -> T[N][K] single fp16.  sel: 0 = W_attn (N=N3), 1 = W_proj
__global__ void transpose_split_kernel(const float* __restrict__ W, int sel)
{
    __shared__ float tile[32][33];
    const int N = sel ? CC : N3;
    __half* Th = sel ? g_wp : g_wa;
    const int n0 = blockIdx.x * 32, k0 = blockIdx.y * 32;
    const int tx = threadIdx.x, ty = threadIdx.y;
#pragma unroll
    for (int j = 0; j < 32; j += 8)
        tile[ty + j][tx] = W[(size_t)(k0 + ty + j) * N + n0 + tx];
    __syncthreads();
#pragma unroll
    for (int j = 0; j < 32; j += 8)
        Th[(size_t)(n0 + ty + j) * CC + k0 + tx] = __float2half_rn(tile[tx][ty + j]);
}

// ---------------------------------------------------------------------------
// fp16 HMMA flash attention: S 2-pass (Q split, K single), PV 2-pass
// (P split in regs, V single).  K/V stage is 2 tiles.
// ---------------------------------------------------------------------------
#define AP        144
#define QB        (2 * 128 * AP)   // Qh + Ql = 36864
#define KVTILE    (64 * AP)        // 9216
#define STG       (2 * KVTILE)     // K, V = 18432
#define ATTN_SMEM (QB + 2 * STG)   // 73728

__device__ __forceinline__ void load_kv_stage(int bh, int kt, uint32_t dstb, int tid) {
    const __half* kb = g_k + ((size_t)bh * TT + kt * 64) * HD;
    const __half* vb = g_vt + (size_t)bh * HD * TT + kt * 64;
#pragma unroll
    for (int i = 0; i < 4; i++) {
        int e = tid + i * 256;            // 0..1023
        int t = e >> 9;                   // 0=K, 1=V
        int idx = e & 511;
        int row = idx >> 3, c = idx & 7;
        const __half* src = (t == 0) ? (kb + (size_t)row * HD + c * 8)
                                     : (vb + (size_t)row * TT + c * 8);
        cp16(dstb + t * KVTILE + row * AP + c * 16, src);
    }
}

__global__ __launch_bounds__(256, 2) void attn_mma()
{
    extern __shared__ char sm[];
    const int tid = threadIdx.x, lane = tid & 31, wid = tid >> 5;
    const int g = lane >> 2, q4 = lane & 3;
    const int qt = blockIdx.x, bh = blockIdx.y;
    const int q0 = qt * 128, wm = wid * 16;
    const uint32_t sb = smem_u32(sm);
    const uint32_t sQh = sb, sQl = sb + 128 * AP;
    const int nkt = 2 * qt + 2;

    const int arow = lane & 15;
    const int achunk = lane >> 4;
    const int brow = (lane & 7) + ((lane >> 4) << 3);
    const int bchunk = (lane >> 3) & 1;

    // Q tiles (hi/lo) -> smem
    {
        const __half* qsrc[2] = {g_qh + ((size_t)bh * TT + q0) * HD,
                                 g_ql + ((size_t)bh * TT + q0) * HD};
#pragma unroll
        for (int i = 0; i < 8; i++) {
            int e = tid + i * 256;
            int bf = e >> 10;
            int idx = e & 1023;
            int row = idx >> 3, c = idx & 7;
            cp16(sb + bf * 128 * AP + row * AP + c * 16,
                 qsrc[bf] + (size_t)row * HD + c * 8);
        }
    }
    load_kv_stage(bh, 0, sb + QB, tid);
    cp_commit();

    float o[8][4];
#pragma unroll
    for (int a = 0; a < 8; a++)
#pragma unroll
        for (int b = 0; b < 4; b++) o[a][b] = 0.f;
    float mr0 = -1e30f, mr1 = -1e30f, l0 = 0.f, l1 = 0.f;

    for (int kt = 0; kt < nkt; kt++) {
        if (kt + 1 < nkt) {
            load_kv_stage(bh, kt + 1, sb + QB + ((kt + 1) & 1) * STG, tid);
            cp_commit();
            cp_wait<1>();
        } else {
            cp_wait<0>();
        }
        __syncthreads();

        const uint32_t st = sb + QB + (kt & 1) * STG;
        const uint32_t sK = st;
        const uint32_t sV = st + KVTILE;

        // ---- S = Q K^T (2-pass: Qh·K + Ql·K) ----
        float s[8][4];
#pragma unroll
        for (int a = 0; a < 8; a++)
#pragma unroll
            for (int b = 0; b < 4; b++) s[a][b] = 0.f;

#pragma unroll
        for (int kc = 0; kc < 4; kc++) {
            uint32_t qh[4], ql[4];
            ldm_x4(qh, sQh + (wm + arow) * AP + kc * 32 + achunk * 16);
            ldm_x4(ql, sQl + (wm + arow) * AP + kc * 32 + achunk * 16);
#pragma unroll
            for (int p = 0; p < 4; p++) {   // nt pairs: nt = 2p, 2p+1
                uint32_t kk2[4];
                ldm_x4(kk2, sK + (p * 16 + brow) * AP + kc * 32 + bchunk * 16);
                mma_f16(s[2 * p],     qh, &kk2[0], s[2 * p]);
                mma_f16(s[2 * p],     ql, &kk2[0], s[2 * p]);
                mma_f16(s[2 * p + 1], qh, &kk2[2], s[2 * p + 1]);
                mma_f16(s[2 * p + 1], ql, &kk2[2], s[2 * p + 1]);
            }
        }

        // ---- causal mask (diagonal tiles only) ----
        if (kt >= 2 * qt) {
            const int r0g = q0 + wm + g;
#pragma unroll
            for (int nt = 0; nt < 8; nt++) {
                const int cb = kt * 64 + nt * 8 + 2 * q4;
                if (cb > r0g)          s[nt][0] = -1e30f;
                if (cb + 1 > r0g)      s[nt][1] = -1e30f;
                if (cb > r0g + 8)      s[nt][2] = -1e30f;
                if (cb + 1 > r0g + 8)  s[nt][3] = -1e30f;
            }
        }

        // ---- online softmax ----
        float mx0 = s[0][0], mx1 = s[0][2];
#pragma unroll
        for (int nt = 0; nt < 8; nt++) {
            mx0 = fmaxf(mx0, fmaxf(s[nt][0], s[nt][1]));
            mx1 = fmaxf(mx1, fmaxf(s[nt][2], s[nt][3]));
        }
        mx0 = fmaxf(mx0, __shfl_xor_sync(0xffffffff, mx0, 1));
        mx0 = fmaxf(mx0, __shfl_xor_sync(0xffffffff, mx0, 2));
        mx1 = fmaxf(mx1, __shfl_xor_sync(0xffffffff, mx1, 1));
        mx1 = fmaxf(mx1, __shfl_xor_sync(0xffffffff, mx1, 2));
        const float mn0 = fmaxf(mr0, mx0), mn1 = fmaxf(mr1, mx1);
        const float f0 = fast_exp(mr0 - mn0), f1 = fast_exp(mr1 - mn1);
        mr0 = mn0; mr1 = mn1;
        l0 *= f0; l1 *= f1;
#pragma unroll
        for (int dt = 0; dt < 8; dt++) {
            o[dt][0] *= f0; o[dt][1] *= f0;
            o[dt][2] *= f1; o[dt][3] *= f1;
        }
        float ps0 = 0.f, ps1 = 0.f;
#pragma unroll
        for (int nt = 0; nt < 8; nt++) {
            s[nt][0] = fast_exp(s[nt][0] - mn0);
            s[nt][1] = fast_exp(s[nt][1] - mn0);
            s[nt][2] = fast_exp(s[nt][2] - mn1);
            s[nt][3] = fast_exp(s[nt][3] - mn1);
            ps0 += s[nt][0] + s[nt][1];
            ps1 += s[nt][2] + s[nt][3];
        }
        l0 += ps0; l1 += ps1;

        // ---- O += P V (2-pass: Ph·V + Pl·V; P fragments in registers) ----
#pragma unroll
        for (int kc2 = 0; kc2 < 4; kc2++) {
            const int nt0 = 2 * kc2, nt1 = nt0 + 1;
            uint32_t aph[4], apl[4];
            {
                float p00 = s[nt0][0], p01 = s[nt0][1], p02 = s[nt0][2], p03 = s[nt0][3];
                float p10 = s[nt1][0], p11 = s[nt1][1], p12 = s[nt1][2], p13 = s[nt1][3];
                __half h00 = __float2half_rn(p00), h01 = __float2half_rn(p01);
                __half h02 = __float2half_rn(p02), h03 = __float2half_rn(p03);
                __half h10 = __float2half_rn(p10), h11 = __float2half_rn(p11);
                __half h12 = __float2half_rn(p12), h13 = __float2half_rn(p13);
                aph[0] = packh(h00, h01);
                aph[1] = packh(h02, h03);
                aph[2] = packh(h10, h11);
                aph[3] = packh(h12, h13);
                apl[0] = packh(__float2half_rn(p00 - __half2float(h00)),
                               __float2half_rn(p01 - __half2float(h01)));
                apl[1] = packh(__float2half_rn(p02 - __half2float(h02)),
                               __float2half_rn(p03 - __half2float(h03)));
                apl[2] = packh(__float2half_rn(p10 - __half2float(h10)),
                               __float2half_rn(p11 - __half2float(h11)));
                apl[3] = packh(__float2half_rn(p12 - __half2float(h12)),
                               __float2half_rn(p13 - __half2float(h13)));
            }
#pragma unroll
            for (int p = 0; p < 4; p++) {   // dt pairs: dt = 2p, 2p+1
                uint32_t vv2[4];
                ldm_x4(vv2, sV + (p * 16 + brow) * AP + kc2 * 32 + bchunk * 16);
                mma_f16(o[2 * p],     aph, &vv2[0], o[2 * p]);
                mma_f16(o[2 * p],     apl, &vv2[0], o[2 * p]);
                mma_f16(o[2 * p + 1], aph, &vv2[2], o[2 * p + 1]);
                mma_f16(o[2 * p + 1], apl, &vv2[2], o[2 * p + 1]);
            }
        }
        __syncthreads();
    }

    // ---- finalize: normalize and write y (split fp16 hi/lo) ----
    l0 += __shfl_xor_sync(0xffffffff, l0, 1);
    l0 += __shfl_xor_sync(0xffffffff, l0, 2);
    l1 += __shfl_xor_sync(0xffffffff, l1, 1);
    l1 += __shfl_xor_sync(0xffffffff, l1, 2);
    const float inv0 = 1.f / l0, inv1 = 1.f / l1;

    const int b = bh / HH, h = bh % HH;
    const int t0 = q0 + wm + g, t1 = t0 + 8;
#pragma unroll
    for (int dt = 0; dt < 8; dt++) {
        const int d = dt * 8 + 2 * q4;
        {
            float vx = o[dt][0] * inv0, vy = o[dt][1] * inv0;
            size_t off = (size_t)(b * TT + t0) * CC + h * HD + d;
            __half hx = __float2half_rn(vx), hy = __float2half_rn(vy);
            *(__half2*)(g_yh + off) = __half2(hx, hy);
            *(__half2*)(g_yl + off) = __half2(__float2half_rn(vx - __half2float(hx)),
                                              __float2half_rn(vy - __half2float(hy)));
        }
        {
            float vx = o[dt][2] * inv1, vy = o[dt][3] * inv1;
            size_t off = (size_t)(b * TT + t1) * CC + h * HD + d;
            __half hx = __float2half_rn(vx), hy = __float2half_rn(vy);
            *(__half2*)(g_yh + off) = __half2(hx, hy);
            *(__half2*)(g_yl + off) = __half2(__float2half_rn(vx - __half2float(hx)),
                                              __float2half_rn(vy - __half2float(hy)));
        }
    }
}

// ---------------------------------------------------------------------------
extern "C" void kernel_launch(void* const* d_in, const int* in_sizes, int n_in,
                              void* d_out, int out_size)
{
    const float* x      = (const float*)d_in[0];
    const float* W_attn = (const float*)d_in[1];
    const float* b_attn = (const float*)d_in[2];
    const float* W_proj = (const float*)d_in[3];
    const float* b_proj = (const float*)d_in[4];
    float* out = (float*)d_out;

    cudaFuncSetAttribute(qkv_mm, cudaFuncAttributeMaxDynamicSharedMemorySize, GEMM_SMEM);
    cudaFuncSetAttribute(proj_mm, cudaFuncAttributeMaxDynamicSharedMemorySize, GEMM_SMEM);
    cudaFuncSetAttribute(attn_mma, cudaFuncAttributeMaxDynamicSharedMemorySize, ATTN_SMEM);

    split_x_kernel<<<(MM * CC / 4 + 255) / 256, 256>>>(x);
    {
        dim3 blk(32, 8);
        transpose_split_kernel<<<dim3(N3 / 32, CC / 32), blk>>>(W_attn, 0);
        transpose_split_kernel<<<dim3(CC / 32, CC / 32), blk>>>(W_proj, 1);
    }
    qkv_mm<<<dim3(N3 / 128, MM / 128), 256, GEMM_SMEM>>>(b_attn);
    attn_mma<<<dim3(TT / 128, BB * HH), 256, ATTN_SMEM>>>();
    proj_mm<<<dim3(CC / 128, MM / 128), 256, GEMM_SMEM>>>(b_proj, out);
}